// round 7
// baseline (speedup 1.0000x reference)
#include <cuda_runtime.h>
#include <cstdint>

#define Bn 16
#define TNEW 8
#define Cdim 1024
#define Hn 16
#define HD 64
#define TPAST 4096
#define TFULL 4104
#define BHN 256     // Bn*Hn
#define NTOK 128    // Bn*TNEW
#define KSQ 8       // q / kv GEMM K-split (KC = 128)
#define KSP 16      // proj GEMM K-split  (KC = 64)
#define ASPLIT 4    // attention key-split
#define NCH 16      // 64-key chunks per attention block

// scratch (no cudaMalloc allowed)
__device__ __align__(16) float g_q[NTOK * Cdim];               // 512 KB
__device__ __align__(16) float g_y[NTOK * Cdim];               // 512 KB
__device__ __align__(16) float g_part_a[KSP * 128 * 1024];     // q + proj partials
__device__ __align__(16) float g_part_kv[KSQ * 128 * 2048];    // kv partials
__device__ float g_pm[BHN * ASPLIT * 8];
__device__ float g_pl[BHN * ASPLIT * 8];
__device__ __align__(16) float g_po[BHN * ASPLIT * 8 * 64];    // 2 MB

__device__ __forceinline__ uint32_t smem_u32(const void* p) {
    return (uint32_t)__cvta_generic_to_shared(p);
}
__device__ __forceinline__ void cp16(uint32_t dst, const void* src) {
    asm volatile("cp.async.cg.shared.global [%0], [%1], 16;\n" :: "r"(dst), "l"(src));
}
__device__ __forceinline__ void cp_commit() {
    asm volatile("cp.async.commit_group;\n");
}
template <int N>
__device__ __forceinline__ void cp_wait() {
    asm volatile("cp.async.wait_group %0;\n" :: "n"(N));
}

// ---------------------------------------------------------------------------
// Split-K GEMM with register double-buffering of the global loads.
// part[ks][m][n] = sum_{k in chunk} A[m][k]*Bw[n][k].  M fixed = 128.
// Grid (N/64, K/KC).  256 threads, 8x4 register tile.
// ---------------------------------------------------------------------------
__global__ void __launch_bounds__(256) gemm_splitk(
    const float* __restrict__ A, const float* __restrict__ Bw,
    float* __restrict__ part, int N, int K, int KC)
{
    __shared__ float As[16][132];
    __shared__ float Bs[16][68];

    int n0 = blockIdx.x * 64;
    int kbase = blockIdx.y * KC;
    int t = threadIdx.x;
    int tx = t & 15, ty = t >> 4;

    const int ar = t >> 1, ac = (t & 1) * 8;
    const int br = t >> 2, bc = (t & 3) * 4;

    float acc[8][4] = {};

    const float* apg = &A[(size_t)ar * K + kbase + ac];
    const float* bpg = &Bw[(size_t)(n0 + br) * K + kbase + bc];
    float4 ra0 = *(const float4*)apg;
    float4 ra1 = *(const float4*)(apg + 4);
    float4 rb  = *(const float4*)bpg;

    for (int kk = 0; kk < KC; kk += 16) {
        As[ac + 0][ar] = ra0.x; As[ac + 1][ar] = ra0.y;
        As[ac + 2][ar] = ra0.z; As[ac + 3][ar] = ra0.w;
        As[ac + 4][ar] = ra1.x; As[ac + 5][ar] = ra1.y;
        As[ac + 6][ar] = ra1.z; As[ac + 7][ar] = ra1.w;
        Bs[bc + 0][br] = rb.x;  Bs[bc + 1][br] = rb.y;
        Bs[bc + 2][br] = rb.z;  Bs[bc + 3][br] = rb.w;
        __syncthreads();

        if (kk + 16 < KC) {
            ra0 = *(const float4*)(apg + kk + 16);
            ra1 = *(const float4*)(apg + kk + 20);
            rb  = *(const float4*)(bpg + kk + 16);
        }

        #pragma unroll
        for (int k = 0; k < 16; k++) {
            float4 a0 = *(const float4*)&As[k][ty * 8];
            float4 a1 = *(const float4*)&As[k][ty * 8 + 4];
            float4 b  = *(const float4*)&Bs[k][tx * 4];
            float a[8] = {a0.x, a0.y, a0.z, a0.w, a1.x, a1.y, a1.z, a1.w};
            float bb[4] = {b.x, b.y, b.z, b.w};
            #pragma unroll
            for (int i = 0; i < 8; i++)
                #pragma unroll
                for (int j = 0; j < 4; j++)
                    acc[i][j] += a[i] * bb[j];
        }
        __syncthreads();
    }

    float* pout = part + (size_t)blockIdx.y * 128 * N;
    #pragma unroll
    for (int i = 0; i < 8; i++) {
        int m = ty * 8 + i;
        float4 w = make_float4(acc[i][0], acc[i][1], acc[i][2], acc[i][3]);
        *(float4*)&pout[(size_t)m * N + n0 + tx * 4] = w;
    }
}

// reduce q partials + bias -> g_q  (128 x 1024)
__global__ void __launch_bounds__(256) reduce_q(
    const float* __restrict__ part, const float* __restrict__ bias,
    float* __restrict__ out)
{
    int idx = blockIdx.x * 256 + threadIdx.x;   // 128 * 256
    int m = idx >> 8, n = idx & 255;
    float4 s = *(const float4*)&bias[n * 4];
    #pragma unroll
    for (int ks = 0; ks < KSQ; ks++) {
        float4 p = *(const float4*)&part[((size_t)ks * 128 + m) * 1024 + n * 4];
        s.x += p.x; s.y += p.y; s.z += p.z; s.w += p.w;
    }
    *(float4*)&out[(size_t)m * 1024 + n * 4] = s;
}

// reduce kv partials + bias -> scatter new k/v rows into the caches
__global__ void __launch_bounds__(256) reduce_kv(
    const float* __restrict__ part, const float* __restrict__ bias,
    float* __restrict__ kout, float* __restrict__ vout)
{
    int idx = blockIdx.x * 256 + threadIdx.x;   // 128 * 512
    int m = idx >> 9, n = idx & 511;            // n4 over 2048 cols
    float4 s = *(const float4*)&bias[n * 4];
    #pragma unroll
    for (int ks = 0; ks < KSQ; ks++) {
        float4 p = *(const float4*)&part[((size_t)ks * 128 + m) * 2048 + n * 4];
        s.x += p.x; s.y += p.y; s.z += p.z; s.w += p.w;
    }
    int c = n * 4;                 // 0..2047 ; <1024 = k_new, else v_new
    int isv = c >> 10;
    int cc = c & 1023;
    int hh = cc >> 6, d = cc & 63;
    int bb = m >> 3, j = m & 7;
    float* dst = isv ? vout : kout;
    *(float4*)&dst[(((size_t)(bb * 16 + hh)) * TFULL + TPAST + j) * 64 + d] = s;
}

// reduce projection partials + bias -> out
__global__ void __launch_bounds__(256) reduce_proj(
    const float* __restrict__ part, const float* __restrict__ bias,
    float* __restrict__ out)
{
    int idx = blockIdx.x * 256 + threadIdx.x;   // 128 * 256
    int m = idx >> 8, n = idx & 255;
    float4 s = *(const float4*)&bias[n * 4];
    #pragma unroll
    for (int ks = 0; ks < KSP; ks++) {
        float4 p = *(const float4*)&part[((size_t)ks * 128 + m) * 1024 + n * 4];
        s.x += p.x; s.y += p.y; s.z += p.z; s.w += p.w;
    }
    *(float4*)&out[(size_t)m * 1024 + n * 4] = s;
}

// ---------------------------------------------------------------------------
// Pipelined split attention over PAST keys only.  grid (BHN, ASPLIT).
// k double-buffered cp.async; v single-buffered deferred; fused cache copy.
// ---------------------------------------------------------------------------
__device__ __forceinline__ void softmax_update10(
    float* Ss, float* m_s, float* l_s, float* f_s, int lane, int wid)
{
    int j = wid;
    float v0 = Ss[lane * 10 + j];
    float v1 = Ss[(lane + 32) * 10 + j];
    float mx = fmaxf(v0, v1);
    #pragma unroll
    for (int o = 16; o; o >>= 1) mx = fmaxf(mx, __shfl_xor_sync(0xffffffffu, mx, o));
    float m_old = m_s[j];
    float m_new = fmaxf(m_old, mx);
    float p0 = __expf(v0 - m_new);
    float p1 = __expf(v1 - m_new);
    Ss[lane * 10 + j] = p0;
    Ss[(lane + 32) * 10 + j] = p1;
    float sum = p0 + p1;
    #pragma unroll
    for (int o = 16; o; o >>= 1) sum += __shfl_xor_sync(0xffffffffu, sum, o);
    if (lane == 0) {
        float f = __expf(m_old - m_new);
        l_s[j] = l_s[j] * f + sum;
        m_s[j] = m_new;
        f_s[j] = f;
    }
}

// dynamic smem layout (bytes):
//   qs: 0..2048 | k_sm: 2048..34816 (2x) | v_sm: 34816..51200 (1x)
//   Ss: 51200..53760 | m/l/f: 53760..53856 | red: 53856..55904
#define ATTN_SMEM 55904

__global__ void __launch_bounds__(256, 4) attn_split(
    const float* __restrict__ past_k, const float* __restrict__ past_v,
    float* __restrict__ kout, float* __restrict__ vout)
{
    extern __shared__ char smraw[];
    float*  qs   = (float*)smraw;
    float4* k_sm = (float4*)(smraw + 2048);
    float4* v_sm = (float4*)(smraw + 34816);
    float*  Ss   = (float*)(smraw + 51200);
    float*  m_s  = (float*)(smraw + 53760);
    float*  l_s  = m_s + 8;
    float*  f_s  = m_s + 16;
    float4* red  = (float4*)(smraw + 53856);

    int bh = blockIdx.x;
    int s  = blockIdx.y;
    int b = bh >> 4, h = bh & 15;
    int t = threadIdx.x, lane = t & 31, wid = t >> 5;

    // load q (scale folded: 1/sqrt(64) = 0.125)
    for (int i = t; i < 512; i += 256) {
        int j = i >> 6, d = i & 63;
        qs[i] = g_q[(size_t)(b * 8 + j) * 1024 + h * 64 + d] * 0.125f;
    }
    if (t < 8) { m_s[t] = -3.0e38f; l_s[t] = 0.f; }

    const float4* ksrc = (const float4*)past_k + (size_t)bh * TPAST * 16;
    const float4* vsrc = (const float4*)past_v + (size_t)bh * TPAST * 16;
    float4* kdst = (float4*)kout + (size_t)bh * TFULL * 16;
    float4* vdst = (float4*)vout + (size_t)bh * TFULL * 16;
    const float4* q4 = (const float4*)qs;
    const float2* v2s = (const float2*)v_sm;

    const int ld_r = t >> 4, ld_d4 = t & 15;
    uint32_t k_b0 = smem_u32(k_sm), v_b0 = smem_u32(v_sm);

    const int j2 = (wid & 3) * 2;
    const int r_sc = (wid >> 2) * 32 + lane;
    const int jp = t >> 6;
    const int rh = (t >> 5) & 1;
    const int d2 = lane;

    float accA0 = 0.f, accA1 = 0.f, accB0 = 0.f, accB1 = 0.f;

    const int c_begin = s * (TPAST / ASPLIT);

    #pragma unroll
    for (int it = 0; it < 4; it++) {
        int r = ld_r + it * 16;
        int sw = r * 16 + (ld_d4 ^ (r & 15));
        cp16(k_b0 + (uint32_t)sw * 16, ksrc + (size_t)(c_begin + r) * 16 + ld_d4);
    }
    cp_commit();

    for (int ci = 0; ci < NCH; ci++) {
        int c0 = c_begin + ci * 64;
        int buf = ci & 1;
        cp_wait<0>();
        __syncthreads();       // sync_a: k(ci) visible; accum(ci-1) done

        #pragma unroll
        for (int it = 0; it < 4; it++) {
            int r = ld_r + it * 16;
            int sw = r * 16 + (ld_d4 ^ (r & 15));
            cp16(v_b0 + (uint32_t)sw * 16, vsrc + (size_t)(c0 + r) * 16 + ld_d4);
        }
        cp_commit();

        bool more = (ci + 1 < NCH);
        if (more) {
            uint32_t kb = k_b0 + (uint32_t)(buf ^ 1) * 16384;
            #pragma unroll
            for (int it = 0; it < 4; it++) {
                int r = ld_r + it * 16;
                int sw = r * 16 + (ld_d4 ^ (r & 15));
                cp16(kb + (uint32_t)sw * 16, ksrc + (size_t)(c0 + 64 + r) * 16 + ld_d4);
            }
            cp_commit();
        }

        const float4* kbp = k_sm + buf * 1024;

        #pragma unroll
        for (int it = 0; it < 4; it++) {
            int r = ld_r + it * 16;
            int sw = r * 16 + (ld_d4 ^ (r & 15));
            __stcs(&kdst[(size_t)(c0 + r) * 16 + ld_d4], kbp[sw]);
        }

        {
            int r = r_sc;
            float s0 = 0.f, s1 = 0.f;
            #pragma unroll
            for (int d4 = 0; d4 < 16; d4++) {
                float4 kv = kbp[r * 16 + (d4 ^ (r & 15))];
                float4 qa = q4[j2 * 16 + d4];
                float4 qb = q4[(j2 + 1) * 16 + d4];
                s0 += kv.x * qa.x + kv.y * qa.y + kv.z * qa.z + kv.w * qa.w;
                s1 += kv.x * qb.x + kv.y * qb.y + kv.z * qb.z + kv.w * qb.w;
            }
            Ss[r * 10 + j2]     = s0;
            Ss[r * 10 + j2 + 1] = s1;
        }
        __syncthreads();       // sync_b
        softmax_update10(Ss, m_s, l_s, f_s, lane, wid);
        if (more) cp_wait<1>(); else cp_wait<0>();
        __syncthreads();       // sync_c

        {
            float f0 = f_s[2 * jp], f1 = f_s[2 * jp + 1];
            accA0 *= f0; accA1 *= f0; accB0 *= f1; accB1 *= f1;
        }
        #pragma unroll
        for (int it = 0; it < 4; it++) {
            int r = ld_r + it * 16;
            int sw = r * 16 + (ld_d4 ^ (r & 15));
            __stcs(&vdst[(size_t)(c0 + r) * 16 + ld_d4], v_sm[sw]);
        }
        {
            int d4 = d2 >> 1, dlo = d2 & 1;
            #pragma unroll 8
            for (int rr = 0; rr < 32; rr++) {
                int r = rh * 32 + rr;
                float2 p = *(const float2*)&Ss[r * 10 + 2 * jp];
                float2 vv = v2s[(r * 16 + (d4 ^ (r & 15))) * 2 + dlo];
                accA0 += p.x * vv.x; accA1 += p.x * vv.y;
                accB0 += p.y * vv.x; accB1 += p.y * vv.y;
            }
        }
    }
    __syncthreads();

    // cross-half reduce + store partials
    if (rh == 1) red[jp * 32 + d2] = make_float4(accA0, accA1, accB0, accB1);
    __syncthreads();
    if (rh == 0) {
        float4 o = red[jp * 32 + d2];
        accA0 += o.x; accA1 += o.y; accB0 += o.z; accB1 += o.w;
        int j0 = 2 * jp, j1 = 2 * jp + 1;
        size_t base = (size_t)(bh * ASPLIT + s) * 8;
        g_po[(base + j0) * 64 + 2 * d2]     = accA0;
        g_po[(base + j0) * 64 + 2 * d2 + 1] = accA1;
        g_po[(base + j1) * 64 + 2 * d2]     = accB0;
        g_po[(base + j1) * 64 + 2 * d2 + 1] = accB1;
    }
    if (t < 8) {
        g_pm[(bh * ASPLIT + s) * 8 + t] = m_s[t];
        g_pl[(bh * ASPLIT + s) * 8 + t] = l_s[t];
    }
}

// ---------------------------------------------------------------------------
// Combine: merge 4 past-split partials AND the 8 new causal keys -> g_y.
// One block per (b,h), 512 threads; reads new k/v from the cache tail.
// ---------------------------------------------------------------------------
__global__ void __launch_bounds__(512) attn_combine(
    const float* __restrict__ kout, const float* __restrict__ vout)
{
    __shared__ float qs[512], kn[512], vn[512];
    __shared__ float Ss[64];

    int bh = blockIdx.x;
    int b = bh >> 4, h = bh & 15;
    int t = threadIdx.x;
    int j = t >> 6, d = t & 63;

    // load q (scaled), new k, new v
    qs[t] = g_q[(size_t)(b * 8 + j) * 1024 + h * 64 + d] * 0.125f;
    kn[t] = kout[((size_t)bh * TFULL + TPAST + j) * 64 + d];
    vn[t] = vout[((size_t)bh * TFULL + TPAST + j) * 64 + d];
    __syncthreads();

    // scores for the 8x8 causal block (64 threads)
    if (t < 64) {
        int jq = t >> 3, r = t & 7;
        float sc = -3.0e38f;
        if (r <= jq) {
            float a = 0.f;
            #pragma unroll
            for (int dd = 0; dd < 64; dd++)
                a += qs[jq * 64 + dd] * kn[r * 64 + dd];
            sc = a;
        }
        Ss[t] = sc;
    }
    __syncthreads();

    float mm[ASPLIT], ll[ASPLIT];
    float m_g = -3.0e38f;
    #pragma unroll
    for (int s = 0; s < ASPLIT; s++) {
        mm[s] = g_pm[(bh * ASPLIT + s) * 8 + j];
        ll[s] = g_pl[(bh * ASPLIT + s) * 8 + j];
        m_g = fmaxf(m_g, mm[s]);
    }
    float sc[8];
    #pragma unroll
    for (int r = 0; r < 8; r++) {
        sc[r] = Ss[j * 8 + r];
        m_g = fmaxf(m_g, sc[r]);
    }
    float l_g = 0.f, o = 0.f;
    #pragma unroll
    for (int s = 0; s < ASPLIT; s++) {
        float w = __expf(mm[s] - m_g);
        l_g += ll[s] * w;
        o += g_po[((size_t)(bh * ASPLIT + s) * 8 + j) * 64 + d] * w;
    }
    #pragma unroll
    for (int r = 0; r < 8; r++) {
        float p = __expf(sc[r] - m_g);   // exp(-inf - m) = 0 handles mask
        l_g += p;
        o += p * vn[r * 64 + d];
    }
    g_y[(size_t)(b * 8 + j) * Cdim + h * 64 + d] = o / l_g;
}

// ---------------------------------------------------------------------------
// kernel_launch: forked-stream capture.
//   main:  gemm_q -> reduce_q -> attn_split ----\
//   s2:    gemm_kv -> reduce_kv (scatter) -------> attn_combine -> proj
// ---------------------------------------------------------------------------
extern "C" void kernel_launch(void* const* d_in, const int* in_sizes, int n_in,
                              void* d_out, int out_size)
{
    const float* x      = (const float*)d_in[0];
    const float* past_k = (const float*)d_in[1];
    const float* past_v = (const float*)d_in[2];
    const float* W_attn = (const float*)d_in[3];
    const float* b_attn = (const float*)d_in[4];
    const float* W_proj = (const float*)d_in[5];
    const float* b_proj = (const float*)d_in[6];

    float* out  = (float*)d_out;
    float* kout = out + (size_t)NTOK * Cdim;
    float* vout = kout + (size_t)BHN * TFULL * HD;

    float* q_ptr  = nullptr;
    float* y_ptr  = nullptr;
    float* pa_ptr = nullptr;
    float* pkv_ptr = nullptr;
    cudaGetSymbolAddress((void**)&q_ptr, g_q);
    cudaGetSymbolAddress((void**)&y_ptr, g_y);
    cudaGetSymbolAddress((void**)&pa_ptr, g_part_a);
    cudaGetSymbolAddress((void**)&pkv_ptr, g_part_kv);

    static cudaStream_t s2 = nullptr;
    static cudaEvent_t e1 = nullptr, e2 = nullptr;
    static int init_done = 0;
    if (!init_done) {
        cudaFuncSetAttribute(attn_split,
            cudaFuncAttributeMaxDynamicSharedMemorySize, ATTN_SMEM);
        cudaStreamCreateWithFlags(&s2, cudaStreamNonBlocking);
        cudaEventCreateWithFlags(&e1, cudaEventDisableTiming);
        cudaEventCreateWithFlags(&e2, cudaEventDisableTiming);
        init_done = 1;
    }

    // fork side stream: K/V projection + scatter into caches
    cudaEventRecord(e1, 0);
    cudaStreamWaitEvent(s2, e1, 0);
    gemm_splitk<<<dim3(32, KSQ), 256, 0, s2>>>(
        x, W_attn + (size_t)1024 * 1024, pkv_ptr, 2048, 1024, 128);
    reduce_kv<<<256, 256, 0, s2>>>(pkv_ptr, b_attn + 1024, kout, vout);
    cudaEventRecord(e2, s2);

    // main stream: q projection + past-key attention
    gemm_splitk<<<dim3(16, KSQ), 256>>>(x, W_attn, pa_ptr, 1024, 1024, 128);
    reduce_q<<<128, 256>>>(pa_ptr, b_attn, q_ptr);
    attn_split<<<dim3(BHN, ASPLIT), 256, ATTN_SMEM>>>(past_k, past_v, kout, vout);

    // join: combine needs new k/v in the caches
    cudaStreamWaitEvent(0, e2, 0);
    attn_combine<<<BHN, 512>>>(kout, vout);

    // output projection
    gemm_splitk<<<dim3(16, KSP), 256>>>(y_ptr, W_proj, pa_ptr, 1024, 1024, 64);
    reduce_proj<<<128, 256>>>(pa_ptr, b_proj, out);
}